// round 16
// baseline (speedup 1.0000x reference)
#include <cuda_runtime.h>

#define NF 16        // filters
#define FF 2000      // features
#define DC 512       // coordinate (reduction) dim
#define NB 64        // batch
#define KNN 8        // neighbors
#define IPAD 2048    // padded feature dim for the packed operand

// Scratch (static device globals — no allocation at runtime)
__device__ float g_Xp[(size_t)NF * DC * IPAD];        // 64 MB packed [f][c][i]
__device__ float g_sq[NF * FF];                       // column squared norms
__device__ float g_dist[(size_t)NF * FF * FF];        // 256 MB distances [f][i][j]

// ---------------------------------------------------------------------------
// sq[f][i] = sum_c coord[c][i][f]^2, emulating XLA's GPU column-reduction
// order bit-exactly (DO NOT TOUCH — verified rel_err == 0.0).
// ---------------------------------------------------------------------------
__global__ __launch_bounds__(1024) void sq_kernel(const float* __restrict__ coord) {
    __shared__ float s[32][33];
    const int tx = threadIdx.x & 31;
    const int ty = threadIdx.x >> 5;
    const int outbase = blockIdx.x * 32;
    const int out = outbase + tx;

    float acc = 0.0f;
    #pragma unroll
    for (int m = 0; m < 16; m++) {
        int c = ty + 32 * m;
        float v = coord[(size_t)c * (FF * NF) + out];
        acc = __fadd_rn(acc, __fmul_rn(v, v));
    }
    s[ty][tx] = acc;
    __syncthreads();

    float v = s[tx][ty];
    #pragma unroll
    for (int off = 16; off; off >>= 1)
        v = __fadd_rn(v, __shfl_down_sync(0xffffffffu, v, off));

    if (tx == 0) {
        int o = outbase + ty;
        int f = o & 15;
        int i = o >> 4;
        g_sq[f * FF + i] = v;
    }
}

// ---------------------------------------------------------------------------
// Pack coords (c, i, f) -> Xp[f][c][i], zero-padding i in [2000, 2048).
// ---------------------------------------------------------------------------
__global__ void pack_kernel(const float* __restrict__ coord) {
    __shared__ float s[64][17];
    const int c = blockIdx.y;
    const int ibase = blockIdx.x * 64;
    const int t = threadIdx.x;

    int il = t >> 2;
    int f0 = (t & 3) * 4;
    float4 v = make_float4(0.f, 0.f, 0.f, 0.f);
    if (ibase + il < FF) {
        v = *(const float4*)(coord + (size_t)c * FF * NF + (size_t)(ibase + il) * NF + f0);
    }
    s[il][f0 + 0] = v.x;
    s[il][f0 + 1] = v.y;
    s[il][f0 + 2] = v.z;
    s[il][f0 + 3] = v.w;
    __syncthreads();

    int i2 = t & 63;
    int fhi = t >> 6;
    #pragma unroll
    for (int pph = 0; pph < 4; pph++) {
        int f = pph * 4 + fhi;
        g_Xp[((size_t)f * DC + c) * IPAD + ibase + i2] = s[i2][f];
    }
}

// ---------------------------------------------------------------------------
// Per-filter syrk + distance epilogue (bit-exact, at the scalar-FFMA issue
// roofline — R13-proven launch_bounds(256,2)).
// filter = fbase + blockIdx.z for chunked pipelining.
// ---------------------------------------------------------------------------
__global__ __launch_bounds__(256, 2) void gram_kernel(int fbase) {
    const int f = fbase + blockIdx.z;

    int p = blockIdx.x;
    int ti = 0;
    while (p >= (16 - ti)) { p -= (16 - ti); ti++; }
    const int tj = ti + p;

    const float* X = g_Xp + (size_t)f * DC * IPAD;
    __shared__ float As[8][128];
    __shared__ float Bs[8][128];

    const int t  = threadIdx.x;
    const int kl = t >> 5;
    const int i4 = (t & 31) << 2;
    const int tx = t & 15;
    const int ty = t >> 4;
    const int Ib = ti << 7;
    const int Jb = tj << 7;

    float acc[8][8];
    #pragma unroll
    for (int u = 0; u < 8; u++)
        #pragma unroll
        for (int v = 0; v < 8; v++) acc[u][v] = 0.0f;

    float4 ra = *(const float4*)(X + (size_t)kl * IPAD + Ib + i4);
    float4 rb = *(const float4*)(X + (size_t)kl * IPAD + Jb + i4);

    for (int k0 = 0; k0 < DC; k0 += 8) {
        *(float4*)&As[kl][i4] = ra;
        *(float4*)&Bs[kl][i4] = rb;
        __syncthreads();
        if (k0 + 8 < DC) {
            ra = *(const float4*)(X + (size_t)(k0 + 8 + kl) * IPAD + Ib + i4);
            rb = *(const float4*)(X + (size_t)(k0 + 8 + kl) * IPAD + Jb + i4);
        }
        #pragma unroll
        for (int kk = 0; kk < 8; kk++) {
            float a[8], b[8];
            *(float4*)&a[0] = *(const float4*)&As[kk][ty * 8];
            *(float4*)&a[4] = *(const float4*)&As[kk][ty * 8 + 4];
            *(float4*)&b[0] = *(const float4*)&Bs[kk][tx * 8];
            *(float4*)&b[4] = *(const float4*)&Bs[kk][tx * 8 + 4];
            #pragma unroll
            for (int u = 0; u < 8; u++)
                #pragma unroll
                for (int v = 0; v < 8; v++)
                    acc[u][v] = fmaf(a[u], b[v], acc[u][v]);
        }
        __syncthreads();
    }

    const int gib = Ib + ty * 8;
    const int gjb = Jb + tx * 8;
    #pragma unroll
    for (int u = 0; u < 8; u++) {
        int gi = gib + u;
        if (gi >= FF) continue;
        float si = g_sq[f * FF + gi];
        #pragma unroll
        for (int v = 0; v < 8; v++) {
            int gj = gjb + v;
            if (gj >= FF) continue;
            float sj = g_sq[f * FF + gj];
            float d = fmaxf(si + sj - 2.0f * acc[u][v], 0.0f);
            g_dist[((size_t)f * FF + gi) * FF + gj] = d;
            if (ti != tj)
                g_dist[((size_t)f * FF + gj) * FF + gi] = d;
        }
    }
}

// ---------------------------------------------------------------------------
// Top-8 smallest per row + FUSED GATHER — warp per row, two-pass sampled
// threshold (R11 logic, rel_err 0.0). After extraction the winner key is
// warp-uniform, so every lane knows all 8 neighbor indices and the warp
// gathers its row's output directly (8 r x 64 b, 16 staged loads + 16
// stores per lane). g_idx and the separate gather kernel are eliminated;
// chunks 0..6's gather traffic hides under gram (issue-bound, 4% DRAM).
// ---------------------------------------------------------------------------
#define SENT_KEY 0x7F7FFFFFFFFFFFFFULL   // (FLT_MAX bits << 32) | 0xFFFFFFFF
#define FMAXV    3.402823466e+38f

__global__ void topk_kernel(int fbase, const float* __restrict__ inputs,
                            float* __restrict__ out) {
    const int wg   = (blockIdx.x * blockDim.x + threadIdx.x) >> 5;  // 0..2*FF-1
    const int lane = threadIdx.x & 31;
    if (wg >= 2 * FF) return;
    const int f = fbase + wg / FF;
    const int i = wg % FF;

    const float4* __restrict__ row4 =
        (const float4*)(g_dist + ((size_t)f * FF + i) * FF);

    // ---- Pass A: per-lane min (staged loads, MLP=4) ----
    float lmin = FMAXV;
    #pragma unroll
    for (int base = 0; base < 500; base += 128) {
        float4 d[4];
        #pragma unroll
        for (int t = 0; t < 4; t++) {
            int m = base + t * 32 + lane;
            d[t] = (m < 500) ? row4[m]
                             : make_float4(FMAXV, FMAXV, FMAXV, FMAXV);
        }
        #pragma unroll
        for (int t = 0; t < 4; t++)
            lmin = fminf(lmin, fminf(fminf(d[t].x, d[t].y),
                                     fminf(d[t].z, d[t].w)));
    }

    // T = 8th-smallest lane minimum (warp-min with retire; tie over-retire
    // only raises T — still a sound upper bound on the global 8th).
    float T;
    {
        float mv = lmin;
        #pragma unroll
        for (int r = 0; r < KNN; r++) {
            float m = mv;
            #pragma unroll
            for (int off = 16; off; off >>= 1)
                m = fminf(m, __shfl_xor_sync(0xffffffffu, m, off));
            T = m;
            if (mv == m) mv = FMAXV;   // retire winner(s)
        }
    }

    // ---- Pass B: exact insert of elements <= T (L1/L2-resident reload) ----
    unsigned long long k0 = SENT_KEY, k1 = SENT_KEY, k2 = SENT_KEY,
                       k3 = SENT_KEY, k4 = SENT_KEY, k5 = SENT_KEY,
                       k6 = SENT_KEY, k7 = SENT_KEY;

#define CSW(a, b) { if ((b) < (a)) { unsigned long long _t = (a); (a) = (b); (b) = _t; } }
#define TOPK_TRY(dv, jv)                                                      \
    if ((dv) <= T) {                                                          \
        unsigned long long key =                                              \
            ((unsigned long long)__float_as_uint(dv) << 32) | (unsigned)(jv); \
        if (key < k7) {                                                       \
            k7 = key;                                                         \
            CSW(k6, k7); CSW(k5, k6); CSW(k4, k5); CSW(k3, k4);               \
            CSW(k2, k3); CSW(k1, k2); CSW(k0, k1);                            \
        }                                                                     \
    }

    #pragma unroll
    for (int base = 0; base < 500; base += 128) {
        float4 d[4];
        int m4[4];
        #pragma unroll
        for (int t = 0; t < 4; t++) {
            m4[t] = base + t * 32 + lane;
            d[t] = (m4[t] < 500) ? row4[m4[t]]
                                 : make_float4(FMAXV, FMAXV, FMAXV, FMAXV);
        }
        #pragma unroll
        for (int t = 0; t < 4; t++) {
            float mn = fminf(fminf(d[t].x, d[t].y), fminf(d[t].z, d[t].w));
            if (mn <= T) {
                int j0 = m4[t] << 2;
                TOPK_TRY(d[t].x, j0 + 0);
                TOPK_TRY(d[t].y, j0 + 1);
                TOPK_TRY(d[t].z, j0 + 2);
                TOPK_TRY(d[t].w, j0 + 3);
            }
        }
    }
#undef TOPK_TRY
#undef CSW

    // Extraction: global min over lane heads; winner shifts its buffer.
    // m is warp-uniform after the butterfly -> all lanes collect idxs[r].
    int idxs[KNN];
    #pragma unroll
    for (int r = 0; r < KNN; r++) {
        unsigned long long m = k0;
        #pragma unroll
        for (int off = 16; off; off >>= 1) {
            unsigned long long o = __shfl_xor_sync(0xffffffffu, m, off);
            m = (o < m) ? o : m;
        }
        if (k0 == m) {
            k0 = k1; k1 = k2; k2 = k3; k3 = k4;
            k4 = k5; k5 = k6; k6 = k7; k7 = 0xFFFFFFFFFFFFFFFFULL;
        }
        idxs[r] = (int)(m & 0xFFFFFFFFu);
    }

    // Fused gather: out[b][i*8+r][f] = inputs[b][idxs[r]][f].
    // Lane covers b = lane and b = lane+32; all 16 loads staged first.
    float vals[2 * KNN];
    #pragma unroll
    for (int r = 0; r < KNN; r++) {
        vals[2 * r + 0] = inputs[((size_t)lane        * FF + idxs[r]) * NF + f];
        vals[2 * r + 1] = inputs[((size_t)(lane + 32) * FF + idxs[r]) * NF + f];
    }
    const size_t orow = (size_t)i * KNN;
    #pragma unroll
    for (int r = 0; r < KNN; r++) {
        out[((size_t)lane        * (FF * KNN) + orow + r) * NF + f] = vals[2 * r + 0];
        out[((size_t)(lane + 32) * (FF * KNN) + orow + r) * NF + f] = vals[2 * r + 1];
    }
}

// ---------------------------------------------------------------------------
// Launcher: pipelined fork/join (capture-legal protocol, R13-proven).
//   S0:    [root] pack, gram chunks (even), final join
//   sGram: gram chunks (odd)
//   sTopk: sq, then topk(+fused gather) chunk c after gram chunk c's event
// 8 uniform chunks of 2 filters (R15's taper + chunked gather reverted).
// ---------------------------------------------------------------------------
extern "C" void kernel_launch(void* const* d_in, const int* in_sizes, int n_in,
                              void* d_out, int out_size) {
    const float* inputs = (const float*)d_in[0];   // (64, 2000, 16)
    const float* coords = (const float*)d_in[1];   // (512, 2000, 16)
    if (n_in >= 2 && in_sizes[0] == DC * FF * NF) {
        coords = (const float*)d_in[0];
        inputs = (const float*)d_in[1];
    }

    static cudaStream_t sGram = nullptr, sTopk = nullptr;
    static cudaEvent_t evRoot, evSq, evHead, evG[8], evT;
    static bool ready = false;
    if (!ready) {
        cudaStreamCreateWithFlags(&sGram, cudaStreamNonBlocking);
        cudaStreamCreateWithFlags(&sTopk, cudaStreamNonBlocking);
        cudaEventCreateWithFlags(&evRoot, cudaEventDisableTiming);
        cudaEventCreateWithFlags(&evSq,   cudaEventDisableTiming);
        cudaEventCreateWithFlags(&evHead, cudaEventDisableTiming);
        for (int c = 0; c < 8; c++)
            cudaEventCreateWithFlags(&evG[c], cudaEventDisableTiming);
        cudaEventCreateWithFlags(&evT, cudaEventDisableTiming);
        ready = true;
    }
    cudaStream_t S0 = 0;

    // Fork: make side streams capture-reachable BEFORE launching on them.
    cudaEventRecord(evRoot, S0);
    cudaStreamWaitEvent(sTopk, evRoot, 0);
    cudaStreamWaitEvent(sGram, evRoot, 0);

    // Head: pack on S0 || sq on sTopk; join into S0 (gram needs both).
    pack_kernel<<<dim3(32, DC), 256, 0, S0>>>(coords);
    sq_kernel<<<FF * NF / 32, 1024, 0, sTopk>>>(coords);
    cudaEventRecord(evSq, sTopk);
    cudaStreamWaitEvent(S0, evSq, 0);
    cudaEventRecord(evHead, S0);
    cudaStreamWaitEvent(sGram, evHead, 0);

    // Pipeline: 8 chunks x 2 filters. Gram alternates S0/sGram; each chunk's
    // event releases topk(+gather) on sTopk.
    for (int c = 0; c < 8; c++) {
        cudaStream_t Sg = (c & 1) ? sGram : S0;
        gram_kernel<<<dim3(136, 1, 2), 256, 0, Sg>>>(c * 2);
        cudaEventRecord(evG[c], Sg);
        cudaStreamWaitEvent(sTopk, evG[c], 0);
        topk_kernel<<<(2 * FF * 32) / 128, 128, 0, sTopk>>>(
            c * 2, inputs, (float*)d_out);
    }

    // Join: S0 waits for sTopk's last topk (covers all work transitively).
    cudaEventRecord(evT, sTopk);
    cudaStreamWaitEvent(S0, evT, 0);
}

// round 17
// speedup vs baseline: 1.1122x; 1.1122x over previous
#include <cuda_runtime.h>

#define NF 16        // filters
#define FF 2000      // features
#define DC 512       // coordinate (reduction) dim
#define NB 64        // batch
#define KNN 8        // neighbors
#define IPAD 2048    // padded feature dim for the packed operand

// Scratch (static device globals — no allocation at runtime)
__device__ float g_Xp[(size_t)NF * DC * IPAD];        // 64 MB packed [f][c][i]
__device__ float g_sq[NF * FF];                       // column squared norms
__device__ float g_dist[(size_t)NF * FF * FF];        // 256 MB distances [f][i][j]
__device__ int   g_idx[FF * KNN * NF];                // neighbor indices [(i*8+k)*16 + f]

// ---------------------------------------------------------------------------
// sq[f][i] = sum_c coord[c][i][f]^2, emulating XLA's GPU column-reduction
// order bit-exactly (DO NOT TOUCH — verified rel_err == 0.0).
// ---------------------------------------------------------------------------
__global__ __launch_bounds__(1024) void sq_kernel(const float* __restrict__ coord) {
    __shared__ float s[32][33];
    const int tx = threadIdx.x & 31;
    const int ty = threadIdx.x >> 5;
    const int outbase = blockIdx.x * 32;
    const int out = outbase + tx;

    float acc = 0.0f;
    #pragma unroll
    for (int m = 0; m < 16; m++) {
        int c = ty + 32 * m;
        float v = coord[(size_t)c * (FF * NF) + out];
        acc = __fadd_rn(acc, __fmul_rn(v, v));
    }
    s[ty][tx] = acc;
    __syncthreads();

    float v = s[tx][ty];
    #pragma unroll
    for (int off = 16; off; off >>= 1)
        v = __fadd_rn(v, __shfl_down_sync(0xffffffffu, v, off));

    if (tx == 0) {
        int o = outbase + ty;
        int f = o & 15;
        int i = o >> 4;
        g_sq[f * FF + i] = v;
    }
}

// ---------------------------------------------------------------------------
// Pack coords (c, i, f) -> Xp[f][c][i], zero-padding i in [2000, 2048).
// ---------------------------------------------------------------------------
__global__ void pack_kernel(const float* __restrict__ coord) {
    __shared__ float s[64][17];
    const int c = blockIdx.y;
    const int ibase = blockIdx.x * 64;
    const int t = threadIdx.x;

    int il = t >> 2;
    int f0 = (t & 3) * 4;
    float4 v = make_float4(0.f, 0.f, 0.f, 0.f);
    if (ibase + il < FF) {
        v = *(const float4*)(coord + (size_t)c * FF * NF + (size_t)(ibase + il) * NF + f0);
    }
    s[il][f0 + 0] = v.x;
    s[il][f0 + 1] = v.y;
    s[il][f0 + 2] = v.z;
    s[il][f0 + 3] = v.w;
    __syncthreads();

    int i2 = t & 63;
    int fhi = t >> 6;
    #pragma unroll
    for (int pph = 0; pph < 4; pph++) {
        int f = pph * 4 + fhi;
        g_Xp[((size_t)f * DC + c) * IPAD + ibase + i2] = s[i2][f];
    }
}

// ---------------------------------------------------------------------------
// Per-filter syrk + distance epilogue (bit-exact, at the scalar-FFMA issue
// roofline — R13-proven launch_bounds(256,2)).
// filter = fbase + blockIdx.z for chunked pipelining.
// ---------------------------------------------------------------------------
__global__ __launch_bounds__(256, 2) void gram_kernel(int fbase) {
    const int f = fbase + blockIdx.z;

    int p = blockIdx.x;
    int ti = 0;
    while (p >= (16 - ti)) { p -= (16 - ti); ti++; }
    const int tj = ti + p;

    const float* X = g_Xp + (size_t)f * DC * IPAD;
    __shared__ float As[8][128];
    __shared__ float Bs[8][128];

    const int t  = threadIdx.x;
    const int kl = t >> 5;
    const int i4 = (t & 31) << 2;
    const int tx = t & 15;
    const int ty = t >> 4;
    const int Ib = ti << 7;
    const int Jb = tj << 7;

    float acc[8][8];
    #pragma unroll
    for (int u = 0; u < 8; u++)
        #pragma unroll
        for (int v = 0; v < 8; v++) acc[u][v] = 0.0f;

    float4 ra = *(const float4*)(X + (size_t)kl * IPAD + Ib + i4);
    float4 rb = *(const float4*)(X + (size_t)kl * IPAD + Jb + i4);

    for (int k0 = 0; k0 < DC; k0 += 8) {
        *(float4*)&As[kl][i4] = ra;
        *(float4*)&Bs[kl][i4] = rb;
        __syncthreads();
        if (k0 + 8 < DC) {
            ra = *(const float4*)(X + (size_t)(k0 + 8 + kl) * IPAD + Ib + i4);
            rb = *(const float4*)(X + (size_t)(k0 + 8 + kl) * IPAD + Jb + i4);
        }
        #pragma unroll
        for (int kk = 0; kk < 8; kk++) {
            float a[8], b[8];
            *(float4*)&a[0] = *(const float4*)&As[kk][ty * 8];
            *(float4*)&a[4] = *(const float4*)&As[kk][ty * 8 + 4];
            *(float4*)&b[0] = *(const float4*)&Bs[kk][tx * 8];
            *(float4*)&b[4] = *(const float4*)&Bs[kk][tx * 8 + 4];
            #pragma unroll
            for (int u = 0; u < 8; u++)
                #pragma unroll
                for (int v = 0; v < 8; v++)
                    acc[u][v] = fmaf(a[u], b[v], acc[u][v]);
        }
        __syncthreads();
    }

    const int gib = Ib + ty * 8;
    const int gjb = Jb + tx * 8;
    #pragma unroll
    for (int u = 0; u < 8; u++) {
        int gi = gib + u;
        if (gi >= FF) continue;
        float si = g_sq[f * FF + gi];
        #pragma unroll
        for (int v = 0; v < 8; v++) {
            int gj = gjb + v;
            if (gj >= FF) continue;
            float sj = g_sq[f * FF + gj];
            float d = fmaxf(si + sj - 2.0f * acc[u][v], 0.0f);
            g_dist[((size_t)f * FF + gi) * FF + gj] = d;
            if (ti != tj)
                g_dist[((size_t)f * FF + gj) * FF + gi] = d;
        }
    }
}

// ---------------------------------------------------------------------------
// Top-8 smallest per row — warp per row, TWO-PASS sampled threshold (R11,
// rel_err 0.0; chunked: filters [fbase, fbase+2)). R13-proven config:
// 128-thread blocks, writes g_idx, NO fused gather.
// ---------------------------------------------------------------------------
#define SENT_KEY 0x7F7FFFFFFFFFFFFFULL   // (FLT_MAX bits << 32) | 0xFFFFFFFF
#define FMAXV    3.402823466e+38f

__global__ void topk_kernel(int fbase) {
    const int wg   = (blockIdx.x * blockDim.x + threadIdx.x) >> 5;  // 0..2*FF-1
    const int lane = threadIdx.x & 31;
    if (wg >= 2 * FF) return;
    const int f = fbase + wg / FF;
    const int i = wg % FF;

    const float4* __restrict__ row4 =
        (const float4*)(g_dist + ((size_t)f * FF + i) * FF);

    // ---- Pass A: per-lane min (staged loads, MLP=4) ----
    float lmin = FMAXV;
    #pragma unroll
    for (int base = 0; base < 500; base += 128) {
        float4 d[4];
        #pragma unroll
        for (int t = 0; t < 4; t++) {
            int m = base + t * 32 + lane;
            d[t] = (m < 500) ? row4[m]
                             : make_float4(FMAXV, FMAXV, FMAXV, FMAXV);
        }
        #pragma unroll
        for (int t = 0; t < 4; t++)
            lmin = fminf(lmin, fminf(fminf(d[t].x, d[t].y),
                                     fminf(d[t].z, d[t].w)));
    }

    // T = 8th-smallest lane minimum (warp-min with retire; tie over-retire
    // only raises T — still a sound upper bound on the global 8th).
    float T;
    {
        float mv = lmin;
        #pragma unroll
        for (int r = 0; r < KNN; r++) {
            float m = mv;
            #pragma unroll
            for (int off = 16; off; off >>= 1)
                m = fminf(m, __shfl_xor_sync(0xffffffffu, m, off));
            T = m;
            if (mv == m) mv = FMAXV;   // retire winner(s)
        }
    }

    // ---- Pass B: exact insert of elements <= T (L1/L2-resident reload) ----
    unsigned long long k0 = SENT_KEY, k1 = SENT_KEY, k2 = SENT_KEY,
                       k3 = SENT_KEY, k4 = SENT_KEY, k5 = SENT_KEY,
                       k6 = SENT_KEY, k7 = SENT_KEY;

#define CSW(a, b) { if ((b) < (a)) { unsigned long long _t = (a); (a) = (b); (b) = _t; } }
#define TOPK_TRY(dv, jv)                                                      \
    if ((dv) <= T) {                                                          \
        unsigned long long key =                                              \
            ((unsigned long long)__float_as_uint(dv) << 32) | (unsigned)(jv); \
        if (key < k7) {                                                       \
            k7 = key;                                                         \
            CSW(k6, k7); CSW(k5, k6); CSW(k4, k5); CSW(k3, k4);               \
            CSW(k2, k3); CSW(k1, k2); CSW(k0, k1);                            \
        }                                                                     \
    }

    #pragma unroll
    for (int base = 0; base < 500; base += 128) {
        float4 d[4];
        int m4[4];
        #pragma unroll
        for (int t = 0; t < 4; t++) {
            m4[t] = base + t * 32 + lane;
            d[t] = (m4[t] < 500) ? row4[m4[t]]
                                 : make_float4(FMAXV, FMAXV, FMAXV, FMAXV);
        }
        #pragma unroll
        for (int t = 0; t < 4; t++) {
            float mn = fminf(fminf(d[t].x, d[t].y), fminf(d[t].z, d[t].w));
            if (mn <= T) {
                int j0 = m4[t] << 2;
                TOPK_TRY(d[t].x, j0 + 0);
                TOPK_TRY(d[t].y, j0 + 1);
                TOPK_TRY(d[t].z, j0 + 2);
                TOPK_TRY(d[t].w, j0 + 3);
            }
        }
    }
#undef TOPK_TRY
#undef CSW

    // Extraction: global min over lane heads; winner shifts its buffer.
    // All static indexing; keys unique (index embedded) -> single winner.
    #pragma unroll
    for (int r = 0; r < KNN; r++) {
        unsigned long long m = k0;
        #pragma unroll
        for (int off = 16; off; off >>= 1) {
            unsigned long long o = __shfl_xor_sync(0xffffffffu, m, off);
            m = (o < m) ? o : m;
        }
        if (k0 == m) {
            k0 = k1; k1 = k2; k2 = k3; k3 = k4;
            k4 = k5; k5 = k6; k6 = k7; k7 = 0xFFFFFFFFFFFFFFFFULL;
        }
        if (lane == 0)
            g_idx[(i * KNN + r) * NF + f] = (int)(m & 0xFFFFFFFFu);
    }
}

// ---------------------------------------------------------------------------
// Gather — out[b][row][c] = inputs[b][ idx[row][c] ][c].
// R17 upgrade (only change vs R13): 4 elements per thread, split across the
// output in quarters (writes stay fully coalesced); idx loads staged, then
// value loads staged -> MLP=4 at both dependence levels. inputs (8 MB) is
// L2-resident, so this collapses the latency-bound tail.
// ---------------------------------------------------------------------------
#define GTOTAL (NB * FF * KNN * NF)
#define GQUART (GTOTAL / 4)

__global__ void gather_kernel(const float* __restrict__ inputs,
                              float* __restrict__ out) {
    int g0 = blockIdx.x * blockDim.x + threadIdx.x;
    if (g0 >= GQUART) return;

    int g[4], r[4];
    #pragma unroll
    for (int q = 0; q < 4; q++) g[q] = g0 + q * GQUART;

    // Stage 1: 4 independent idx loads
    #pragma unroll
    for (int q = 0; q < 4; q++) {
        int c   = g[q] & 15;
        int row = (g[q] >> 4) % (FF * KNN);
        r[q] = g_idx[row * NF + c];
    }
    // Stage 2: 4 independent value loads
    float v[4];
    #pragma unroll
    for (int q = 0; q < 4; q++) {
        int c = g[q] & 15;
        int b = g[q] / (FF * KNN * NF);
        v[q] = inputs[((size_t)b * FF + r[q]) * NF + c];
    }
    // Stage 3: 4 coalesced stores
    #pragma unroll
    for (int q = 0; q < 4; q++) out[g[q]] = v[q];
}

// ---------------------------------------------------------------------------
// Launcher: pipelined fork/join (capture-legal protocol, R13-proven, verbatim).
//   S0:    [root] pack, gram chunks (even), gather
//   sGram: gram chunks (odd)
//   sTopk: sq, then topk chunk c after gram chunk c's event
// ---------------------------------------------------------------------------
extern "C" void kernel_launch(void* const* d_in, const int* in_sizes, int n_in,
                              void* d_out, int out_size) {
    const float* inputs = (const float*)d_in[0];   // (64, 2000, 16)
    const float* coords = (const float*)d_in[1];   // (512, 2000, 16)
    if (n_in >= 2 && in_sizes[0] == DC * FF * NF) {
        coords = (const float*)d_in[0];
        inputs = (const float*)d_in[1];
    }

    static cudaStream_t sGram = nullptr, sTopk = nullptr;
    static cudaEvent_t evRoot, evSq, evHead, evG[8], evT;
    static bool ready = false;
    if (!ready) {
        cudaStreamCreateWithFlags(&sGram, cudaStreamNonBlocking);
        cudaStreamCreateWithFlags(&sTopk, cudaStreamNonBlocking);
        cudaEventCreateWithFlags(&evRoot, cudaEventDisableTiming);
        cudaEventCreateWithFlags(&evSq,   cudaEventDisableTiming);
        cudaEventCreateWithFlags(&evHead, cudaEventDisableTiming);
        for (int c = 0; c < 8; c++)
            cudaEventCreateWithFlags(&evG[c], cudaEventDisableTiming);
        cudaEventCreateWithFlags(&evT, cudaEventDisableTiming);
        ready = true;
    }
    cudaStream_t S0 = 0;

    // Fork: make side streams capture-reachable BEFORE launching on them.
    cudaEventRecord(evRoot, S0);
    cudaStreamWaitEvent(sTopk, evRoot, 0);
    cudaStreamWaitEvent(sGram, evRoot, 0);

    // Head: pack on S0 || sq on sTopk; join into S0 (gram needs both).
    pack_kernel<<<dim3(32, DC), 256, 0, S0>>>(coords);
    sq_kernel<<<FF * NF / 32, 1024, 0, sTopk>>>(coords);
    cudaEventRecord(evSq, sTopk);
    cudaStreamWaitEvent(S0, evSq, 0);
    cudaEventRecord(evHead, S0);
    cudaStreamWaitEvent(sGram, evHead, 0);

    // Pipeline: 8 chunks x 2 filters. Gram alternates S0/sGram; each chunk's
    // event releases its topk on sTopk (dist slab L2-hot).
    for (int c = 0; c < 8; c++) {
        cudaStream_t Sg = (c & 1) ? sGram : S0;
        gram_kernel<<<dim3(136, 1, 2), 256, 0, Sg>>>(c * 2);
        cudaEventRecord(evG[c], Sg);
        cudaStreamWaitEvent(sTopk, evG[c], 0);
        topk_kernel<<<(2 * FF * 32) / 128, 128, 0, sTopk>>>(c * 2);
    }

    // Join: gather needs all g_idx; S0 must also see sGram's last chunk.
    cudaEventRecord(evT, sTopk);
    cudaStreamWaitEvent(S0, evT, 0);
    gather_kernel<<<(GQUART + 255) / 256, 256, 0, S0>>>(inputs, (float*)d_out);
}